// round 14
// baseline (speedup 1.0000x reference)
#include <cuda_runtime.h>
#include <cuda_bf16.h>
#include <mma.h>
#include <math.h>
#include <stdint.h>

using namespace nvcuda;
typedef long long ll;

#define H_ 8
#define D_ 1024
#define S_ 1024
#define MID_ 2048
#define SOUT_ 512
#define HD_ 8192

// ---------------- scratch (device globals; no runtime allocation) ----------------
// fp32
__device__ float g_sk [(ll)8 * D_ * S_];          // k pre-transpose (33.5 MB)
__device__ float g_y2t[(ll)D_ * S_];              // y2^T (4 MB)
// bf16 hi/lo plane arenas (hi at +0, lo at +plane_stride)
__device__ __nv_bfloat16 P_w   [(ll)2 * 16777216]; // weights, reused      (67 MB)
__device__ __nv_bfloat16 P_act [(ll)2 * 16777216]; // z (8 heads) / x1     (67 MB)
__device__ __nv_bfloat16 P_qkv [(ll)2 * 3 * D_ * S_];
__device__ __nv_bfloat16 P_q   [(ll)2 * 8 * D_ * S_];
__device__ __nv_bfloat16 P_k   [(ll)2 * 8 * D_ * S_];
__device__ __nv_bfloat16 P_v   [(ll)2 * 8 * D_ * S_];
__device__ __nv_bfloat16 P_b   [(ll)2 * 8 * S_ * S_];
__device__ __nv_bfloat16 P_att [(ll)2 * 8 * D_ * S_];
__device__ __nv_bfloat16 P_misc[(ll)2 * 2097152];  // inp / y1t / y3 planes (8.4 MB)
__device__ __nv_bfloat16 P_h   [(ll)2 * D_ * S_];  // h planes / x2 planes  (4.2 MB)

// ---------------- helpers ----------------
__device__ __forceinline__ uint32_t smem_u32(const void* p) {
    uint32_t a;
    asm("{ .reg .u64 t; cvta.to.shared.u64 t, %1; cvt.u32.u64 %0, t; }" : "=r"(a) : "l"(p));
    return a;
}
#define CP16(dst, src) asm volatile("cp.async.cg.shared.global [%0], [%1], 16;" :: "r"(dst), "l"(src))

__device__ __forceinline__ void split2(float x, __nv_bfloat16& h, __nv_bfloat16& l) {
    h = __float2bfloat16(x);
    l = __float2bfloat16(x - __bfloat162float(h));
}

// ---------------- convert: fp32 -> bf16 hi/lo planes (no transpose) ----------------
template<bool RELU>
__global__ __launch_bounds__(256) void conv_nt(const float* __restrict__ in,
                                               __nv_bfloat16* __restrict__ out,
                                               ll inStride, ll outStride, ll plS)
{
    const float* src = in + (ll)blockIdx.y * inStride;
    __nv_bfloat16* oh = out + (ll)blockIdx.y * outStride;
    ll i = ((ll)blockIdx.x * 256 + threadIdx.x) * 4;
    float4 v = *(const float4*)(src + i);
    if (RELU) {
        v.x = fmaxf(v.x, 0.f); v.y = fmaxf(v.y, 0.f);
        v.z = fmaxf(v.z, 0.f); v.w = fmaxf(v.w, 0.f);
    }
    __nv_bfloat16 h[4], l[4];
    split2(v.x, h[0], l[0]); split2(v.y, h[1], l[1]);
    split2(v.z, h[2], l[2]); split2(v.w, h[3], l[3]);
    *(uint2*)(oh + i)       = *(uint2*)h;
    *(uint2*)(oh + plS + i) = *(uint2*)l;
}

// ---------------- convert with transpose: [R][C] fp32 -> [C][R] planes ----------------
template<bool RELU>
__global__ __launch_bounds__(256) void conv_t(const float* __restrict__ in,
                                              __nv_bfloat16* __restrict__ out,
                                              int R, int C, ll inStride, ll outStride, ll plS)
{
    const float* src = in + (ll)blockIdx.z * inStride;
    __nv_bfloat16* oh = out + (ll)blockIdx.z * outStride;
    __shared__ __nv_bfloat16 th[32][33], tl[32][33];
    const int c0 = blockIdx.x * 32, r0 = blockIdx.y * 32;
    const int tx = threadIdx.x, ty = threadIdx.y;
#pragma unroll
    for (int i = 0; i < 4; i++) {
        int r = r0 + ty + i * 8;
        float x = src[(ll)r * C + c0 + tx];
        if (RELU) x = fmaxf(x, 0.f);
        __nv_bfloat16 hh, lll;
        split2(x, hh, lll);
        th[ty + i * 8][tx] = hh;
        tl[ty + i * 8][tx] = lll;
    }
    __syncthreads();
#pragma unroll
    for (int i = 0; i < 4; i++) {
        int c = c0 + ty + i * 8;
        oh[(ll)c * R + r0 + tx]       = th[tx][ty + i * 8];
        oh[plS + (ll)c * R + r0 + tx] = tl[tx][ty + i * 8];
    }
}

// ---------------- wmma split-bf16 GEMM ----------------
// A planes: hi at A+bz*sA, lo at +aPl. B planes likewise (+bPl).
// EPI: 0 = fp32 C, 1 = tanh fp32 C, 2 = relu hi/lo planes C (+cPl), 3 = hi/lo planes C.
#define PA 40
#define PB 136
static constexpr int A_PL = 128 * PA;
static constexpr int B_PL = 32 * PB;
static constexpr int B_BASE = 4 * A_PL;
static constexpr int GSM = (4 * A_PL + 4 * B_PL) * 2;  // 75776 B (epilogue needs 64 KB)

template<int EPI>
__global__ __launch_bounds__(256) void wgemm(
    const __nv_bfloat16* __restrict__ A, const __nv_bfloat16* __restrict__ B,
    void* __restrict__ Cv, int M, int N, int K,
    ll sA, ll sB, ll sC, ll aPl, ll bPl, ll cPl)
{
    extern __shared__ __nv_bfloat16 smn[];
    const int tid = threadIdx.x;
    const int bz = blockIdx.z;
    const __nv_bfloat16* Ab = A + (ll)bz * sA;
    const __nv_bfloat16* Bb = B + (ll)bz * sB;
    const int bM = blockIdx.y * 128, bN = blockIdx.x * 128;

    auto loadStage = [&](int c, int stage) {
        const int kt = c * 32;
#pragma unroll
        for (int p = 0; p < 2; p++) {
            const __nv_bfloat16* src = Ab + p * aPl;
            __nv_bfloat16* db = smn + (stage * 2 + p) * A_PL;
#pragma unroll
            for (int i = 0; i < 2; i++) {
                int sid = tid + i * 256;
                int row = sid >> 2, seg = sid & 3;
                uint32_t d = smem_u32(db + row * PA + seg * 8);
                CP16(d, src + (ll)(bM + row) * K + kt + seg * 8);
            }
        }
#pragma unroll
        for (int p = 0; p < 2; p++) {
            const __nv_bfloat16* src = Bb + p * bPl;
            __nv_bfloat16* db = smn + B_BASE + (stage * 2 + p) * B_PL;
#pragma unroll
            for (int i = 0; i < 2; i++) {
                int sid = tid + i * 256;
                int row = sid >> 4, seg = sid & 15;
                uint32_t d = smem_u32(db + row * PB + seg * 8);
                CP16(d, src + (ll)(kt + row) * N + bN + seg * 8);
            }
        }
        asm volatile("cp.async.commit_group;");
    };

    wmma::fragment<wmma::accumulator, 16, 16, 16, float> acc[4][2];
#pragma unroll
    for (int i = 0; i < 4; i++)
#pragma unroll
        for (int j = 0; j < 2; j++) wmma::fill_fragment(acc[i][j], 0.f);

    const int wid = tid >> 5;
    const int wm = (wid >> 2) * 64;
    const int wn = (wid & 3) * 32;
    const int nch = K / 32;

    loadStage(0, 0);
    for (int c = 0; c < nch; c++) {
        const int stage = c & 1;
        if (c + 1 < nch) {
            loadStage(c + 1, stage ^ 1);
            asm volatile("cp.async.wait_group 1;");
        } else {
            asm volatile("cp.async.wait_group 0;");
        }
        __syncthreads();

        __nv_bfloat16* a0 = smn + (stage * 2 + 0) * A_PL;
        __nv_bfloat16* a1 = smn + (stage * 2 + 1) * A_PL;
        __nv_bfloat16* b0 = smn + B_BASE + (stage * 2 + 0) * B_PL;
        __nv_bfloat16* b1 = smn + B_BASE + (stage * 2 + 1) * B_PL;

#pragma unroll
        for (int ks = 0; ks < 2; ks++) {
            wmma::fragment<wmma::matrix_a, 16, 16, 16, __nv_bfloat16, wmma::row_major> af[4];
            wmma::fragment<wmma::matrix_b, 16, 16, 16, __nv_bfloat16, wmma::row_major> bh[2], bl[2];
#pragma unroll
            for (int i = 0; i < 4; i++)
                wmma::load_matrix_sync(af[i], a0 + (wm + i * 16) * PA + ks * 16, PA);
#pragma unroll
            for (int j = 0; j < 2; j++)
                wmma::load_matrix_sync(bh[j], b0 + (ks * 16) * PB + wn + j * 16, PB);
#pragma unroll
            for (int j = 0; j < 2; j++)
                wmma::load_matrix_sync(bl[j], b1 + (ks * 16) * PB + wn + j * 16, PB);
#pragma unroll
            for (int i = 0; i < 4; i++)
#pragma unroll
                for (int j = 0; j < 2; j++)
                    wmma::mma_sync(acc[i][j], af[i], bh[j], acc[i][j]);
#pragma unroll
            for (int i = 0; i < 4; i++)
#pragma unroll
                for (int j = 0; j < 2; j++)
                    wmma::mma_sync(acc[i][j], af[i], bl[j], acc[i][j]);
#pragma unroll
            for (int i = 0; i < 4; i++)
                wmma::load_matrix_sync(af[i], a1 + (wm + i * 16) * PA + ks * 16, PA);
#pragma unroll
            for (int i = 0; i < 4; i++)
#pragma unroll
                for (int j = 0; j < 2; j++)
                    wmma::mma_sync(acc[i][j], af[i], bh[j], acc[i][j]);
        }
        __syncthreads();
    }

    if (EPI <= 1) {
        float* Cb = (float*)Cv + (ll)bz * sC;
#pragma unroll
        for (int i = 0; i < 4; i++)
#pragma unroll
            for (int j = 0; j < 2; j++) {
                if (EPI == 1) {
#pragma unroll
                    for (int e = 0; e < acc[i][j].num_elements; e++)
                        acc[i][j].x[e] = tanhf(acc[i][j].x[e]);
                }
                wmma::store_matrix_sync(Cb + (ll)(bM + wm + i * 16) * N + bN + wn + j * 16,
                                        acc[i][j], N, wmma::mem_row_major);
            }
    } else {
        // stage through smem, emit hi/lo bf16 planes (optionally fused ReLU)
        float* esm = (float*)smn + wid * 2048;   // 64x32 per warp
#pragma unroll
        for (int i = 0; i < 4; i++)
#pragma unroll
            for (int j = 0; j < 2; j++)
                wmma::store_matrix_sync(esm + (i * 16) * 32 + j * 16, acc[i][j], 32,
                                        wmma::mem_row_major);
        __syncwarp();
        __nv_bfloat16* Ch = (__nv_bfloat16*)Cv + (ll)bz * sC;
        const int lane = tid & 31;
#pragma unroll 8
        for (int r = 0; r < 64; r++) {
            float x = esm[r * 32 + lane];
            if (EPI == 2) x = fmaxf(x, 0.f);
            __nv_bfloat16 h, l;
            split2(x, h, l);
            ll off = (ll)(bM + wm + r) * N + bN + wn + lane;
            Ch[off]       = h;
            Ch[off + cPl] = l;
        }
    }
}

// ---------------- fused residual + LayerNorm -> bf16 planes ----------------
// out planes[d][s] = split( maybe_relu( LN(inp[d,:] + y2t[d,:]) * gamma + beta ) )
template<bool RELU>
__global__ __launch_bounds__(256) void add_ln_kernel(
    const float* __restrict__ base, const float* __restrict__ y2t,
    const float* __restrict__ gamma, const float* __restrict__ beta,
    __nv_bfloat16* __restrict__ outP)
{
    const int d   = blockIdx.x;
    const int tid = threadIdx.x;
    __shared__ float xs[S_];
    __shared__ float red[256];

    float lsum = 0.f;
    for (int s = tid; s < S_; s += 256) {
        float x = base[(ll)d * S_ + s] + y2t[(ll)d * S_ + s];
        xs[s] = x;
        lsum += x;
    }
    red[tid] = lsum;
    __syncthreads();
    for (int off = 128; off > 0; off >>= 1) {
        if (tid < off) red[tid] += red[tid + off];
        __syncthreads();
    }
    const float mu = red[0] * (1.f / S_);
    __syncthreads();

    float lvar = 0.f;
    for (int s = tid; s < S_; s += 256) {
        float t = xs[s] - mu;
        lvar += t * t;
    }
    red[tid] = lvar;
    __syncthreads();
    for (int off = 128; off > 0; off >>= 1) {
        if (tid < off) red[tid] += red[tid + off];
        __syncthreads();
    }
    const float rstd = rsqrtf(red[0] * (1.f / S_) + 1e-6f);

    const ll DS = (ll)D_ * S_;
    for (int s = tid; s < S_; s += 256) {
        float v = (xs[s] - mu) * rstd * gamma[s] + beta[s];
        if (RELU) v = fmaxf(v, 0.f);
        __nv_bfloat16 h, l;
        split2(v, h, l);
        outP[(ll)d * S_ + s]      = h;
        outP[DS + (ll)d * S_ + s] = l;
    }
}

// ---------------- host-side launchers ----------------
static void convNT(const float* in, __nv_bfloat16* out, ll nElems,
                   ll inStride, ll outStride, ll plS, int batch, bool relu) {
    dim3 g((unsigned)(nElems / 1024), batch);
    if (relu) conv_nt<true ><<<g, 256>>>(in, out, inStride, outStride, plS);
    else      conv_nt<false><<<g, 256>>>(in, out, inStride, outStride, plS);
}
static void convT(const float* in, __nv_bfloat16* out, int R, int C,
                  ll inStride, ll outStride, ll plS, int batch, bool relu) {
    dim3 g(C / 32, R / 32, batch);
    dim3 b(32, 8);
    if (relu) conv_t<true ><<<g, b>>>(in, out, R, C, inStride, outStride, plS);
    else      conv_t<false><<<g, b>>>(in, out, R, C, inStride, outStride, plS);
}
template<int EPI>
static void tgemm(const __nv_bfloat16* A, const __nv_bfloat16* B, void* C,
                  int M, int N, int K, ll sA, ll sB, ll sC,
                  ll aPl, ll bPl, ll cPl, int batch) {
    cudaFuncSetAttribute(wgemm<EPI>, cudaFuncAttributeMaxDynamicSharedMemorySize, GSM);
    dim3 grid(N / 128, M / 128, batch);
    wgemm<EPI><<<grid, 256, GSM>>>(A, B, C, M, N, K, sA, sB, sC, aPl, bPl, cPl);
}

static void run_mha(__nv_bfloat16* qkvP,    // [2][3][D][S] relu planes
                    const float* W1, const float* W2,
                    const float* cw1, const float* cw2,
                    __nv_bfloat16* pw, __nv_bfloat16* pact,
                    __nv_bfloat16* pq, __nv_bfloat16* pk, __nv_bfloat16* pv,
                    __nv_bfloat16* pb, __nv_bfloat16* patt, __nv_bfloat16* pmisc,
                    float* sk, float* y2t)
{
    const ll DS = (ll)D_ * S_, DM = (ll)D_ * MID_, MS = (ll)MID_ * S_, SS = (ll)S_ * S_;
    for (int q = 0; q < 3; q++) {
        // z[h] = relu(qkv_q) @ W1[h,q]^T  -> relu planes
        convT(W1 + (ll)q * MS, pw, MID_, S_, 3 * MS, MS, 8 * MS, 8, false);
        tgemm<2>(qkvP + (ll)q * DS, pw, pact, D_, MID_, S_,
                 0, MS, DM, 3 * DS, 8 * MS, 8 * DM, 8);
        // s[h,q] = relu(z) @ W2[h,q]^T
        convT(W2 + (ll)q * MS, pw, S_, MID_, 3 * MS, MS, 8 * MS, 8, false);
        if (q == 0)
            tgemm<3>(pact, pw, pq, D_, S_, MID_, DM, MS, DS, 8 * DM, 8 * MS, 8 * DS, 8);
        else if (q == 1)
            tgemm<0>(pact, pw, sk, D_, S_, MID_, DM, MS, DS, 8 * DM, 8 * MS, 0, 8);
        else
            tgemm<3>(pact, pw, pv, D_, S_, MID_, DM, MS, DS, 8 * DM, 8 * MS, 8 * DS, 8);
    }
    // k^T planes
    convT(sk, pk, D_, S_, DS, DS, 8 * DS, 8, false);
    // b[h] = k^T @ q  (no relu)
    tgemm<3>(pk, pq, pb, S_, S_, D_, DS, DS, SS, 8 * DS, 8 * DS, 8 * SS, 8);
    // att[h] = v @ b  -> relu planes (cat consumed through relu)
    tgemm<2>(pv, pb, patt, D_, S_, S_, DS, SS, DS, 8 * DS, 8 * SS, 8 * DS, 8);
    // y1^T = cw1 @ relu(cat)  -> relu planes
    convNT(cw1, pw, (ll)MID_ * HD_, 0, 0, (ll)MID_ * HD_, 1, false);
    tgemm<2>(pw, patt, pmisc, MID_, S_, HD_, 0, 0, 0,
             (ll)MID_ * HD_, 8 * DS, MS, 1);
    // y2^T = cw2 @ relu(y1)  -> fp32
    convNT(cw2, pw, (ll)D_ * MID_, 0, 0, (ll)D_ * MID_, 1, false);
    tgemm<0>(pw, pmisc, y2t, D_, S_, MID_, 0, 0, 0, (ll)D_ * MID_, MS, 0, 1);
}

extern "C" void kernel_launch(void* const* d_in, const int* in_sizes, int n_in,
                              void* d_out, int out_size)
{
    const float* inp    = (const float*)d_in[0];
    const float* enc_k  = (const float*)d_in[1];
    const float* enc_v  = (const float*)d_in[2];
    const float* w_qkv1 = (const float*)d_in[3];
    const float* w_qkv2 = (const float*)d_in[4];
    const float* mh1_W1 = (const float*)d_in[5];
    const float* mh1_W2 = (const float*)d_in[6];
    const float* mh2_W1 = (const float*)d_in[7];
    const float* mh2_W2 = (const float*)d_in[8];
    const float* c1_w1  = (const float*)d_in[9];
    const float* c1_w2  = (const float*)d_in[10];
    const float* c2_w1  = (const float*)d_in[11];
    const float* c2_w2  = (const float*)d_in[12];
    const float* l1_w1  = (const float*)d_in[13];
    const float* l1_w2  = (const float*)d_in[14];
    const float* l2_w1  = (const float*)d_in[15];
    const float* l2_w2  = (const float*)d_in[16];
    const float* gamma  = (const float*)d_in[17];
    const float* beta   = (const float*)d_in[18];
    float* out = (float*)d_out;

    void *a0, *a1, *a2, *a3, *a4, *a5, *a6, *a7, *a8, *a9, *a10, *a11;
    cudaGetSymbolAddress(&a0,  g_sk);
    cudaGetSymbolAddress(&a1,  g_y2t);
    cudaGetSymbolAddress(&a2,  P_w);
    cudaGetSymbolAddress(&a3,  P_act);
    cudaGetSymbolAddress(&a4,  P_qkv);
    cudaGetSymbolAddress(&a5,  P_q);
    cudaGetSymbolAddress(&a6,  P_k);
    cudaGetSymbolAddress(&a7,  P_v);
    cudaGetSymbolAddress(&a8,  P_b);
    cudaGetSymbolAddress(&a9,  P_att);
    cudaGetSymbolAddress(&a10, P_misc);
    cudaGetSymbolAddress(&a11, P_h);
    float* sk  = (float*)a0;  float* y2t = (float*)a1;
    __nv_bfloat16* pw    = (__nv_bfloat16*)a2;
    __nv_bfloat16* pact  = (__nv_bfloat16*)a3;
    __nv_bfloat16* pqkv  = (__nv_bfloat16*)a4;
    __nv_bfloat16* pq    = (__nv_bfloat16*)a5;
    __nv_bfloat16* pk    = (__nv_bfloat16*)a6;
    __nv_bfloat16* pv    = (__nv_bfloat16*)a7;
    __nv_bfloat16* pb    = (__nv_bfloat16*)a8;
    __nv_bfloat16* patt  = (__nv_bfloat16*)a9;
    __nv_bfloat16* pmisc = (__nv_bfloat16*)a10;
    __nv_bfloat16* ph    = (__nv_bfloat16*)a11;

    const ll DS = (ll)D_ * S_, DD = (ll)D_ * D_, DM = (ll)D_ * MID_;
    const ll MSo = (ll)MID_ * SOUT_, DSo = (ll)D_ * SOUT_, SM = (ll)S_ * MID_;

    // qkv1 = w_qkv1 @ inp  (batch 3) -> relu planes
    convNT(w_qkv1, pw, DD, DD, DD, 3 * DD, 3, false);
    convNT(inp, pmisc, DS, 0, 0, DS, 1, false);
    tgemm<2>(pw, pmisc, pqkv, D_, S_, D_, DD, 0, DS, 3 * DD, DS, 3 * DS, 3);

    // ---- block 1 ----
    run_mha(pqkv, mh1_W1, mh1_W2, c1_w1, c1_w2,
            pw, pact, pq, pk, pv, pb, patt, pmisc, sk, y2t);
    add_ln_kernel<false><<<D_, 256>>>(inp, y2t, gamma, beta, ph);   // h1 planes (raw)

    // q2 = w_qkv2[0] @ h1 -> relu planes into qkv slot 0
    convNT(w_qkv2, pw, DD, 0, 0, DD, 1, false);
    tgemm<2>(pw, ph, pqkv, D_, S_, D_, 0, 0, 0, DD, DS, 3 * DS, 1);
    // enc_k / enc_v -> relu planes into slots 1, 2
    convNT(enc_k, pqkv + DS,     DS, 0, 0, 3 * DS, 1, true);
    convNT(enc_v, pqkv + 2 * DS, DS, 0, 0, 3 * DS, 1, true);

    // ---- block 2 ----
    run_mha(pqkv, mh2_W1, mh2_W2, c2_w1, c2_w2,
            pw, pact, pq, pk, pv, pb, patt, pmisc, sk, y2t);
    add_ln_kernel<true><<<D_, 256>>>(inp, y2t, gamma, beta, ph);    // h2 planes (relu)

    // ---- final MLP stack ----
    // x1 = relu(h2) @ l1_w1^T -> relu planes
    convT(l1_w1, pw, MID_, S_, 0, 0, SM, 1, false);
    tgemm<2>(ph, pw, pact, D_, MID_, S_, 0, 0, 0, DS, SM, DM, 1);
    // x2 = relu(x1) @ l1_w2^T -> relu planes
    convT(l1_w2, pw, SOUT_, MID_, 0, 0, MSo, 1, false);
    tgemm<2>(pact, pw, ph, D_, SOUT_, MID_, 0, 0, 0, DM, MSo, DSo, 1);
    // y3 = relu(x2) @ l2_w1^T -> relu planes
    convT(l2_w1, pw, MID_, SOUT_, 0, 0, MSo, 1, false);
    tgemm<2>(ph, pw, pmisc, D_, MID_, SOUT_, 0, 0, 0, DSo, MSo, DM, 1);
    // out = tanh(relu(y3) @ l2_w2^T)
    convT(l2_w2, pw, SOUT_, MID_, 0, 0, MSo, 1, false);
    tgemm<1>(pmisc, pw, out, D_, SOUT_, MID_, 0, 0, 0, DM, MSo, 0, 1);
}

// round 15
// speedup vs baseline: 1.6635x; 1.6635x over previous
#include <cuda_runtime.h>
#include <cuda_bf16.h>
#include <mma.h>
#include <math.h>
#include <stdint.h>

using namespace nvcuda;
typedef long long ll;

#define H_ 8
#define D_ 1024
#define S_ 1024
#define MID_ 2048
#define SOUT_ 512

// ---------------- scratch (device globals; no runtime allocation) ----------------
__device__ float g_qkv[(ll)3 * D_ * S_];
__device__ float g_z  [(ll)H_ * D_ * MID_];
__device__ float g_s  [(ll)H_ * 3 * D_ * S_];
__device__ float g_b  [(ll)H_ * S_ * S_];
__device__ float g_att[(ll)H_ * D_ * S_];
__device__ float g_y1 [(ll)S_ * MID_];
__device__ float g_y2 [(ll)S_ * D_];
__device__ float g_h  [(ll)D_ * S_];
__device__ float g_q2 [(ll)D_ * S_];
__device__ float g_x1 [(ll)D_ * MID_];
__device__ float g_x2 [(ll)D_ * SOUT_];
__device__ float g_y3 [(ll)D_ * MID_];
// bf16 hi/lo operand arenas: [batch][2 planes][R*C]
__device__ __nv_bfloat16 g_cA[(ll)8 * 2 * D_ * MID_];
__device__ __nv_bfloat16 g_cB[(ll)8 * 2 * MID_ * S_];

// ---------------- helpers ----------------
__device__ __forceinline__ uint32_t smem_u32(const void* p) {
    uint32_t a;
    asm("{ .reg .u64 t; cvta.to.shared.u64 t, %1; cvt.u32.u64 %0, t; }" : "=r"(a) : "l"(p));
    return a;
}
#define CP16(dst, src) asm volatile("cp.async.cg.shared.global [%0], [%1], 16;" :: "r"(dst), "l"(src))

__device__ __forceinline__ void split2(float x, __nv_bfloat16& h, __nv_bfloat16& l) {
    h = __float2bfloat16(x);
    l = __float2bfloat16(x - __bfloat162float(h));
}

// ---------------- convert: fp32 -> bf16 hi/lo planes (no transpose) ----------------
template<bool RELU>
__global__ __launch_bounds__(256) void conv_nt(const float* __restrict__ in,
                                               __nv_bfloat16* __restrict__ out,
                                               ll inStride, ll outStride, int nElems)
{
    const float* src = in + (ll)blockIdx.y * inStride;
    __nv_bfloat16* oh = out + (ll)blockIdx.y * outStride;
    __nv_bfloat16* olo = oh + nElems;
    int i = (blockIdx.x * 256 + threadIdx.x) * 4;
    float4 v = *(const float4*)(src + i);
    if (RELU) {
        v.x = fmaxf(v.x, 0.f); v.y = fmaxf(v.y, 0.f);
        v.z = fmaxf(v.z, 0.f); v.w = fmaxf(v.w, 0.f);
    }
    __nv_bfloat16 h[4], l[4];
    split2(v.x, h[0], l[0]); split2(v.y, h[1], l[1]);
    split2(v.z, h[2], l[2]); split2(v.w, h[3], l[3]);
    *(uint2*)(oh  + i) = *(uint2*)h;
    *(uint2*)(olo + i) = *(uint2*)l;
}

// ---------------- convert with transpose ----------------
template<bool RELU>
__global__ __launch_bounds__(256) void conv_t(const float* __restrict__ in,
                                              __nv_bfloat16* __restrict__ out,
                                              int R, int C, ll inStride, ll outStride)
{
    const float* src = in + (ll)blockIdx.z * inStride;
    __nv_bfloat16* oh = out + (ll)blockIdx.z * outStride;
    __nv_bfloat16* olo = oh + (ll)R * C;
    __shared__ __nv_bfloat16 th[32][33], tl[32][33];
    const int c0 = blockIdx.x * 32, r0 = blockIdx.y * 32;
    const int tx = threadIdx.x, ty = threadIdx.y;
#pragma unroll
    for (int i = 0; i < 4; i++) {
        int r = r0 + ty + i * 8;
        float x = src[(ll)r * C + c0 + tx];
        if (RELU) x = fmaxf(x, 0.f);
        __nv_bfloat16 hh, lll;
        split2(x, hh, lll);
        th[ty + i * 8][tx] = hh;
        tl[ty + i * 8][tx] = lll;
    }
    __syncthreads();
#pragma unroll
    for (int i = 0; i < 4; i++) {
        int c = c0 + ty + i * 8;
        oh [(ll)c * R + r0 + tx] = th[tx][ty + i * 8];
        olo[(ll)c * R + r0 + tx] = tl[tx][ty + i * 8];
    }
}

// ---------------- wmma split-bf16 GEMM (128x128 tile) ----------------
#define PA 40
#define PB 136
static constexpr int A_PL = 128 * PA;
static constexpr int B_PL = 32 * PB;
static constexpr int B_BASE = 4 * A_PL;
static constexpr int GSM = (4 * A_PL + 4 * B_PL) * 2;

template<int EPI>
__global__ __launch_bounds__(256) void wgemm(
    const __nv_bfloat16* __restrict__ A, const __nv_bfloat16* __restrict__ B,
    float* __restrict__ C, int M, int N, int K, ll sA, ll sB, ll sC)
{
    extern __shared__ __nv_bfloat16 smn[];
    const int tid = threadIdx.x;
    const __nv_bfloat16* Ab = A + (ll)blockIdx.z * sA;
    const __nv_bfloat16* Bb = B + (ll)blockIdx.z * sB;
    float* Cb = C + (ll)blockIdx.z * sC;
    const ll aPlane = (ll)M * K, bPlane = (ll)K * N;
    const int bM = blockIdx.y * 128, bN = blockIdx.x * 128;

    auto loadStage = [&](int c, int stage) {
        const int kt = c * 32;
#pragma unroll
        for (int p = 0; p < 2; p++) {
            const __nv_bfloat16* src = Ab + p * aPlane;
            __nv_bfloat16* db = smn + (stage * 2 + p) * A_PL;
#pragma unroll
            for (int i = 0; i < 2; i++) {
                int sid = tid + i * 256;
                int row = sid >> 2, seg = sid & 3;
                uint32_t d = smem_u32(db + row * PA + seg * 8);
                CP16(d, src + (ll)(bM + row) * K + kt + seg * 8);
            }
        }
#pragma unroll
        for (int p = 0; p < 2; p++) {
            const __nv_bfloat16* src = Bb + p * bPlane;
            __nv_bfloat16* db = smn + B_BASE + (stage * 2 + p) * B_PL;
#pragma unroll
            for (int i = 0; i < 2; i++) {
                int sid = tid + i * 256;
                int row = sid >> 4, seg = sid & 15;
                uint32_t d = smem_u32(db + row * PB + seg * 8);
                CP16(d, src + (ll)(kt + row) * N + bN + seg * 8);
            }
        }
        asm volatile("cp.async.commit_group;");
    };

    wmma::fragment<wmma::accumulator, 16, 16, 16, float> acc[4][2];
#pragma unroll
    for (int i = 0; i < 4; i++)
#pragma unroll
        for (int j = 0; j < 2; j++) wmma::fill_fragment(acc[i][j], 0.f);

    const int wid = tid >> 5;
    const int wm = (wid >> 2) * 64;
    const int wn = (wid & 3) * 32;
    const int nch = K / 32;

    loadStage(0, 0);
    for (int c = 0; c < nch; c++) {
        const int stage = c & 1;
        if (c + 1 < nch) {
            loadStage(c + 1, stage ^ 1);
            asm volatile("cp.async.wait_group 1;");
        } else {
            asm volatile("cp.async.wait_group 0;");
        }
        __syncthreads();

        __nv_bfloat16* a0 = smn + (stage * 2 + 0) * A_PL;
        __nv_bfloat16* a1 = smn + (stage * 2 + 1) * A_PL;
        __nv_bfloat16* b0 = smn + B_BASE + (stage * 2 + 0) * B_PL;
        __nv_bfloat16* b1 = smn + B_BASE + (stage * 2 + 1) * B_PL;

#pragma unroll
        for (int ks = 0; ks < 2; ks++) {
            wmma::fragment<wmma::matrix_a, 16, 16, 16, __nv_bfloat16, wmma::row_major> af[4];
            wmma::fragment<wmma::matrix_b, 16, 16, 16, __nv_bfloat16, wmma::row_major> bh[2], bl[2];
#pragma unroll
            for (int i = 0; i < 4; i++)
                wmma::load_matrix_sync(af[i], a0 + (wm + i * 16) * PA + ks * 16, PA);
#pragma unroll
            for (int j = 0; j < 2; j++)
                wmma::load_matrix_sync(bh[j], b0 + (ks * 16) * PB + wn + j * 16, PB);
#pragma unroll
            for (int j = 0; j < 2; j++)
                wmma::load_matrix_sync(bl[j], b1 + (ks * 16) * PB + wn + j * 16, PB);
#pragma unroll
            for (int i = 0; i < 4; i++)
#pragma unroll
                for (int j = 0; j < 2; j++)
                    wmma::mma_sync(acc[i][j], af[i], bh[j], acc[i][j]);
#pragma unroll
            for (int i = 0; i < 4; i++)
#pragma unroll
                for (int j = 0; j < 2; j++)
                    wmma::mma_sync(acc[i][j], af[i], bl[j], acc[i][j]);
#pragma unroll
            for (int i = 0; i < 4; i++)
                wmma::load_matrix_sync(af[i], a1 + (wm + i * 16) * PA + ks * 16, PA);
#pragma unroll
            for (int i = 0; i < 4; i++)
#pragma unroll
                for (int j = 0; j < 2; j++)
                    wmma::mma_sync(acc[i][j], af[i], bh[j], acc[i][j]);
        }
        __syncthreads();
    }

#pragma unroll
    for (int i = 0; i < 4; i++)
#pragma unroll
        for (int j = 0; j < 2; j++) {
            if (EPI == 1) {
#pragma unroll
                for (int e = 0; e < acc[i][j].num_elements; e++)
                    acc[i][j].x[e] = tanhf(acc[i][j].x[e]);
            }
            wmma::store_matrix_sync(Cb + (ll)(bM + wm + i * 16) * N + bN + wn + j * 16,
                                    acc[i][j], N, wmma::mem_row_major);
        }
}

// ---------------- wmma split-bf16 GEMM (256x128 tile, 64x64 warp tiles) ----------------
// For the big batched GEMMs: better load:mma ratio (16 loads per 48 mmas).
static constexpr int A_PL2 = 256 * PA;            // 10240 elems
static constexpr int B_BASE2 = 4 * A_PL2;         // after 2 stages x 2 planes of A
static constexpr int GSM2 = (4 * A_PL2 + 4 * B_PL) * 2;  // 116736 B

__global__ __launch_bounds__(256) void wgemm256(
    const __nv_bfloat16* __restrict__ A, const __nv_bfloat16* __restrict__ B,
    float* __restrict__ C, int M, int N, int K, ll sA, ll sB, ll sC)
{
    extern __shared__ __nv_bfloat16 smn[];
    const int tid = threadIdx.x;
    const __nv_bfloat16* Ab = A + (ll)blockIdx.z * sA;
    const __nv_bfloat16* Bb = B + (ll)blockIdx.z * sB;
    float* Cb = C + (ll)blockIdx.z * sC;
    const ll aPlane = (ll)M * K, bPlane = (ll)K * N;
    const int bM = blockIdx.y * 256, bN = blockIdx.x * 128;

    auto loadStage = [&](int c, int stage) {
        const int kt = c * 32;
#pragma unroll
        for (int p = 0; p < 2; p++) {
            const __nv_bfloat16* src = Ab + p * aPlane;
            __nv_bfloat16* db = smn + (stage * 2 + p) * A_PL2;
#pragma unroll
            for (int i = 0; i < 4; i++) {
                int sid = tid + i * 256;
                int row = sid >> 2, seg = sid & 3;
                uint32_t d = smem_u32(db + row * PA + seg * 8);
                CP16(d, src + (ll)(bM + row) * K + kt + seg * 8);
            }
        }
#pragma unroll
        for (int p = 0; p < 2; p++) {
            const __nv_bfloat16* src = Bb + p * bPlane;
            __nv_bfloat16* db = smn + B_BASE2 + (stage * 2 + p) * B_PL;
#pragma unroll
            for (int i = 0; i < 2; i++) {
                int sid = tid + i * 256;
                int row = sid >> 4, seg = sid & 15;
                uint32_t d = smem_u32(db + row * PB + seg * 8);
                CP16(d, src + (ll)(kt + row) * N + bN + seg * 8);
            }
        }
        asm volatile("cp.async.commit_group;");
    };

    wmma::fragment<wmma::accumulator, 16, 16, 16, float> acc[4][4];
#pragma unroll
    for (int i = 0; i < 4; i++)
#pragma unroll
        for (int j = 0; j < 4; j++) wmma::fill_fragment(acc[i][j], 0.f);

    const int wid = tid >> 5;
    const int wm = (wid >> 1) * 64;   // 0..192
    const int wn = (wid & 1) * 64;    // 0 or 64
    const int nch = K / 32;

    loadStage(0, 0);
    for (int c = 0; c < nch; c++) {
        const int stage = c & 1;
        if (c + 1 < nch) {
            loadStage(c + 1, stage ^ 1);
            asm volatile("cp.async.wait_group 1;");
        } else {
            asm volatile("cp.async.wait_group 0;");
        }
        __syncthreads();

        __nv_bfloat16* a0 = smn + (stage * 2 + 0) * A_PL2;
        __nv_bfloat16* a1 = smn + (stage * 2 + 1) * A_PL2;
        __nv_bfloat16* b0 = smn + B_BASE2 + (stage * 2 + 0) * B_PL;
        __nv_bfloat16* b1 = smn + B_BASE2 + (stage * 2 + 1) * B_PL;

#pragma unroll
        for (int ks = 0; ks < 2; ks++) {
            wmma::fragment<wmma::matrix_a, 16, 16, 16, __nv_bfloat16, wmma::row_major> af[4];
            wmma::fragment<wmma::matrix_b, 16, 16, 16, __nv_bfloat16, wmma::row_major> bh[4], bl[4];
#pragma unroll
            for (int i = 0; i < 4; i++)
                wmma::load_matrix_sync(af[i], a0 + (wm + i * 16) * PA + ks * 16, PA);
#pragma unroll
            for (int j = 0; j < 4; j++)
                wmma::load_matrix_sync(bh[j], b0 + (ks * 16) * PB + wn + j * 16, PB);
#pragma unroll
            for (int j = 0; j < 4; j++)
                wmma::load_matrix_sync(bl[j], b1 + (ks * 16) * PB + wn + j * 16, PB);
#pragma unroll
            for (int i = 0; i < 4; i++)
#pragma unroll
                for (int j = 0; j < 4; j++)
                    wmma::mma_sync(acc[i][j], af[i], bh[j], acc[i][j]);
#pragma unroll
            for (int i = 0; i < 4; i++)
#pragma unroll
                for (int j = 0; j < 4; j++)
                    wmma::mma_sync(acc[i][j], af[i], bl[j], acc[i][j]);
#pragma unroll
            for (int i = 0; i < 4; i++)
                wmma::load_matrix_sync(af[i], a1 + (wm + i * 16) * PA + ks * 16, PA);
#pragma unroll
            for (int i = 0; i < 4; i++)
#pragma unroll
                for (int j = 0; j < 4; j++)
                    wmma::mma_sync(acc[i][j], af[i], bh[j], acc[i][j]);
        }
        __syncthreads();
    }

#pragma unroll
    for (int i = 0; i < 4; i++)
#pragma unroll
        for (int j = 0; j < 4; j++)
            wmma::store_matrix_sync(Cb + (ll)(bM + wm + i * 16) * N + bN + wn + j * 16,
                                    acc[i][j], N, wmma::mem_row_major);
}

// ---------------- fused residual + transpose + LayerNorm ----------------
__global__ __launch_bounds__(256) void add_ln_kernel(
    const float* __restrict__ base, const float* __restrict__ yT,
    const float* __restrict__ gamma, const float* __restrict__ beta,
    float* __restrict__ out)
{
    const int d   = blockIdx.x;
    const int tid = threadIdx.x;
    __shared__ float xs[S_];
    __shared__ float red[256];

    float lsum = 0.f;
    for (int s = tid; s < S_; s += 256) {
        float x = base[(ll)d * S_ + s] + yT[(ll)s * D_ + d];
        xs[s] = x;
        lsum += x;
    }
    red[tid] = lsum;
    __syncthreads();
    for (int off = 128; off > 0; off >>= 1) {
        if (tid < off) red[tid] += red[tid + off];
        __syncthreads();
    }
    const float mu = red[0] * (1.f / S_);
    __syncthreads();

    float lvar = 0.f;
    for (int s = tid; s < S_; s += 256) {
        float t = xs[s] - mu;
        lvar += t * t;
    }
    red[tid] = lvar;
    __syncthreads();
    for (int off = 128; off > 0; off >>= 1) {
        if (tid < off) red[tid] += red[tid + off];
        __syncthreads();
    }
    const float rstd = rsqrtf(red[0] * (1.f / S_) + 1e-6f);

    for (int s = tid; s < S_; s += 256)
        out[(ll)d * S_ + s] = (xs[s] - mu) * rstd * gamma[s] + beta[s];
}

// ---------------- host-side launchers ----------------
static void convNT(const float* in, __nv_bfloat16* out, ll nElems,
                   ll inStride, ll outStride, int batch, bool relu) {
    dim3 g((unsigned)(nElems / 1024), batch);
    if (relu) conv_nt<true ><<<g, 256>>>(in, out, inStride, outStride, (int)nElems);
    else      conv_nt<false><<<g, 256>>>(in, out, inStride, outStride, (int)nElems);
}
static void convT(const float* in, __nv_bfloat16* out, int R, int C,
                  ll inStride, ll outStride, int batch, bool relu) {
    dim3 g(C / 32, R / 32, batch);
    dim3 b(32, 8);
    if (relu) conv_t<true ><<<g, b>>>(in, out, R, C, inStride, outStride);
    else      conv_t<false><<<g, b>>>(in, out, R, C, inStride, outStride);
}
template<int EPI>
static void tgemm(const __nv_bfloat16* A, const __nv_bfloat16* B, float* C,
                  int M, int N, int K, ll sA, ll sB, ll sC, int batch) {
    cudaFuncSetAttribute(wgemm<EPI>, cudaFuncAttributeMaxDynamicSharedMemorySize, GSM);
    dim3 grid(N / 128, M / 128, batch);
    wgemm<EPI><<<grid, 256, GSM>>>(A, B, C, M, N, K, sA, sB, sC);
}
static void tgemm256(const __nv_bfloat16* A, const __nv_bfloat16* B, float* C,
                     int M, int N, int K, ll sA, ll sB, ll sC, int batch) {
    cudaFuncSetAttribute(wgemm256, cudaFuncAttributeMaxDynamicSharedMemorySize, GSM2);
    dim3 grid(N / 128, M / 256, batch);
    wgemm256<<<grid, 256, GSM2>>>(A, B, C, M, N, K, sA, sB, sC);
}

static void run_mha(const float* const qkvp[3],
                    const float* W1, const float* W2,
                    const float* cw1, const float* cw2,
                    __nv_bfloat16* cA, __nv_bfloat16* cB,
                    float* z, float* sb, float* bb, float* att,
                    float* y1, float* y2)
{
    const ll DS = (ll)D_ * S_, DM = (ll)D_ * MID_, MS = (ll)MID_ * S_, SS = (ll)S_ * S_;
    for (int q = 0; q < 3; q++) {
        // z[h] = relu(qkv_q) @ W1[h,q]^T
        convNT(qkvp[q], cA, DS, 0, 0, 1, true);
        convT (W1 + q * MS, cB, MID_, S_, 3 * MS, 2 * MS, 8, false);
        tgemm256(cA, cB, z, D_, MID_, S_, 0, 2 * MS, DM, 8);
        // s[h,q] = relu(z[h]) @ W2[h,q]^T
        convNT(z, cA, DM, DM, 2 * DM, 8, true);
        convT (W2 + q * MS, cB, S_, MID_, 3 * MS, 2 * MS, 8, false);
        tgemm256(cA, cB, sb + q * DS, D_, S_, MID_, 2 * DM, 2 * MS, 3 * DS, 8);
    }
    // b[h] = k[h]^T @ q[h]
    convT (sb + 1 * DS, cA, D_, S_, 3 * DS, 2 * DS, 8, false);
    convNT(sb + 0 * DS, cB, DS, 3 * DS, 2 * DS, 8, false);
    tgemm256(cA, cB, bb, S_, S_, D_, 2 * DS, 2 * DS, SS, 8);
    // att[h] = v[h] @ b[h]
    convNT(sb + 2 * DS, cA, DS, 3 * DS, 2 * DS, 8, false);
    convNT(bb, cB, SS, SS, 2 * SS, 8, false);
    tgemm256(cA, cB, att, D_, S_, S_, 2 * DS, 2 * SS, DS, 8);
    // y1 = relu(cat^T) @ cw1^T
    convT (att, cA, H_ * D_, S_, 0, 0, 1, true);
    convT (cw1, cB, MID_, H_ * D_, 0, 0, 1, false);
    tgemm<0>(cA, cB, y1, S_, MID_, H_ * D_, 0, 0, 0, 1);
    // y2 = relu(y1) @ cw2^T
    convNT(y1, cA, (ll)S_ * MID_, 0, 0, 1, true);
    convT (cw2, cB, D_, MID_, 0, 0, 1, false);
    tgemm<0>(cA, cB, y2, S_, D_, MID_, 0, 0, 0, 1);
}

extern "C" void kernel_launch(void* const* d_in, const int* in_sizes, int n_in,
                              void* d_out, int out_size)
{
    const float* inp    = (const float*)d_in[0];
    const float* enc_k  = (const float*)d_in[1];
    const float* enc_v  = (const float*)d_in[2];
    const float* w_qkv1 = (const float*)d_in[3];
    const float* w_qkv2 = (const float*)d_in[4];
    const float* mh1_W1 = (const float*)d_in[5];
    const float* mh1_W2 = (const float*)d_in[6];
    const float* mh2_W1 = (const float*)d_in[7];
    const float* mh2_W2 = (const float*)d_in[8];
    const float* c1_w1  = (const float*)d_in[9];
    const float* c1_w2  = (const float*)d_in[10];
    const float* c2_w1  = (const float*)d_in[11];
    const float* c2_w2  = (const float*)d_in[12];
    const float* l1_w1  = (const float*)d_in[13];
    const float* l1_w2  = (const float*)d_in[14];
    const float* l2_w1  = (const float*)d_in[15];
    const float* l2_w2  = (const float*)d_in[16];
    const float* gamma  = (const float*)d_in[17];
    const float* beta   = (const float*)d_in[18];
    float* out = (float*)d_out;

    void *p_qkv, *p_z, *p_s, *p_b, *p_att, *p_y1, *p_y2, *p_h, *p_q2, *p_x1, *p_x2, *p_y3, *p_cA, *p_cB;
    cudaGetSymbolAddress(&p_qkv, g_qkv);
    cudaGetSymbolAddress(&p_z,   g_z);
    cudaGetSymbolAddress(&p_s,   g_s);
    cudaGetSymbolAddress(&p_b,   g_b);
    cudaGetSymbolAddress(&p_att, g_att);
    cudaGetSymbolAddress(&p_y1,  g_y1);
    cudaGetSymbolAddress(&p_y2,  g_y2);
    cudaGetSymbolAddress(&p_h,   g_h);
    cudaGetSymbolAddress(&p_q2,  g_q2);
    cudaGetSymbolAddress(&p_x1,  g_x1);
    cudaGetSymbolAddress(&p_x2,  g_x2);
    cudaGetSymbolAddress(&p_y3,  g_y3);
    cudaGetSymbolAddress(&p_cA,  g_cA);
    cudaGetSymbolAddress(&p_cB,  g_cB);
    float* qkv = (float*)p_qkv;  float* z   = (float*)p_z;
    float* sb  = (float*)p_s;    float* bb  = (float*)p_b;
    float* att = (float*)p_att;  float* y1  = (float*)p_y1;
    float* y2  = (float*)p_y2;   float* hh  = (float*)p_h;
    float* q2  = (float*)p_q2;   float* x1  = (float*)p_x1;
    float* x2  = (float*)p_x2;   float* y3  = (float*)p_y3;
    __nv_bfloat16* cA = (__nv_bfloat16*)p_cA;
    __nv_bfloat16* cB = (__nv_bfloat16*)p_cB;

    const ll DS = (ll)D_ * S_, DD = (ll)D_ * D_;

    // qkv1[q] = w_qkv1[q] @ inp  (batch 3; B shared)
    convNT(w_qkv1, cA, DD, DD, 2 * DD, 3, false);
    convNT(inp, cB, DS, 0, 0, 1, false);
    tgemm<0>(cA, cB, qkv, D_, S_, D_, 2 * DD, 0, DS, 3);

    // ---- block 1 ----
    {
        const float* qp[3] = { qkv, qkv + DS, qkv + 2 * DS };
        run_mha(qp, mh1_W1, mh1_W2, c1_w1, c1_w2, cA, cB, z, sb, bb, att, y1, y2);
    }
    add_ln_kernel<<<D_, 256>>>(inp, y2, gamma, beta, hh);   // h1

    // q2 = w_qkv2[0] @ h1
    convNT(w_qkv2, cA, DD, 0, 0, 1, false);
    convNT(hh, cB, DS, 0, 0, 1, false);
    tgemm<0>(cA, cB, q2, D_, S_, D_, 0, 0, 0, 1);

    // ---- block 2 ----
    {
        const float* qp[3] = { q2, enc_k, enc_v };
        run_mha(qp, mh2_W1, mh2_W2, c2_w1, c2_w2, cA, cB, z, sb, bb, att, y1, y2);
    }
    add_ln_kernel<<<D_, 256>>>(inp, y2, gamma, beta, hh);   // h2

    // ---- final MLP stack ----
    convNT(hh, cA, DS, 0, 0, 1, true);
    convT (l1_w1, cB, MID_, S_, 0, 0, 1, false);
    tgemm<0>(cA, cB, x1, D_, MID_, S_, 0, 0, 0, 1);

    convNT(x1, cA, (ll)D_ * MID_, 0, 0, 1, true);
    convT (l1_w2, cB, SOUT_, MID_, 0, 0, 1, false);
    tgemm<0>(cA, cB, x2, D_, SOUT_, MID_, 0, 0, 0, 1);

    convNT(x2, cA, (ll)D_ * SOUT_, 0, 0, 1, true);
    convT (l2_w1, cB, MID_, SOUT_, 0, 0, 1, false);
    tgemm<0>(cA, cB, y3, D_, MID_, SOUT_, 0, 0, 0, 1);

    convNT(y3, cA, (ll)D_ * MID_, 0, 0, 1, true);
    convT (l2_w2, cB, SOUT_, MID_, 0, 0, 1, false);
    tgemm<1>(cA, cB, out, D_, SOUT_, MID_, 0, 0, 0, 1);
}